// round 2
// baseline (speedup 1.0000x reference)
#include <cuda_runtime.h>
#include <stdint.h>

// MeanAggregator: out[b, :] = mean over {neighbours[b,0..9], nodes[b]} of features[idx, :]
// B = 100000, K = 10, N = 1000000, D = 128 (fp32)
// NOTE: JAX default config downcasts int64 -> int32, so indices are int32 on device.
//
// Layout: one warp per output row b. Lane l handles float4 element l (D=128 = 32 float4).
// Each of the 11 gathered rows is a fully coalesced 512B read across the warp.

#define B_NODES   100000
#define K_NEIGH   10
#define D_DIM     128
#define D_VEC     (D_DIM / 4)   // 32 float4 per row == 1 per lane

__global__ __launch_bounds__(256, 4)
void mean_agg_kernel(const int*    __restrict__ nodes,
                     const int*    __restrict__ neighbours,
                     const float4* __restrict__ features,
                     float4*       __restrict__ out)
{
    const int warp = (blockIdx.x * blockDim.x + threadIdx.x) >> 5;
    const int lane = threadIdx.x & 31;
    if (warp >= B_NODES) return;

    // Gather the 11 row indices (converged loads -> broadcast in L1).
    int idx[K_NEIGH + 1];
#pragma unroll
    for (int k = 0; k < K_NEIGH; ++k)
        idx[k] = neighbours[warp * K_NEIGH + k];
    idx[K_NEIGH] = nodes[warp];

    // Front-batch the 11 independent float4 gathers for max MLP.
    float4 v[K_NEIGH + 1];
#pragma unroll
    for (int k = 0; k < K_NEIGH + 1; ++k)
        v[k] = __ldg(&features[(long long)idx[k] * D_VEC + lane]);

    float4 acc = make_float4(0.f, 0.f, 0.f, 0.f);
#pragma unroll
    for (int k = 0; k < K_NEIGH + 1; ++k) {
        acc.x += v[k].x;
        acc.y += v[k].y;
        acc.z += v[k].z;
        acc.w += v[k].w;
    }

    const float s = 1.0f / (float)(K_NEIGH + 1);
    acc.x *= s; acc.y *= s; acc.z *= s; acc.w *= s;

    out[(long long)warp * D_VEC + lane] = acc;
}

extern "C" void kernel_launch(void* const* d_in, const int* in_sizes, int n_in,
                              void* d_out, int out_size)
{
    const int*    nodes      = (const int*)d_in[0];
    const int*    neighbours = (const int*)d_in[1];
    const float4* features   = (const float4*)d_in[2];
    float4*       out        = (float4*)d_out;

    // One warp per row: B warps -> B*32 threads.
    const int threads = 256;                     // 8 warps / block
    const int blocks  = (B_NODES * 32 + threads - 1) / threads;  // 12500
    mean_agg_kernel<<<blocks, threads>>>(nodes, neighbours, features, out);
}